// round 14
// baseline (speedup 1.0000x reference)
#include <cuda_runtime.h>
#include <cuda_bf16.h>
#include <math.h>
#include <stdint.h>

#define BN 8192
#define DD 512
#define MARGIN 0.3f
#define INF 3.4e38f
#define INF_BITS 0x7F800000

#define SROW 144                    // smem row stride bytes (128B data + 16 pad)
#define TILE_B (128 * SROW)         // 18432 B per matrix tile (128 rows x 64 bf16)
#define STAGE_B (4 * TILE_B)        // Ahi, Alo, Bhi, Blo
#define DYN_SMEM (2 * STAGE_B)      // double buffered = 147456 B

// -------- device scratch --------
__device__ float g_fn[(size_t)BN * DD];           // normalized fp32 (16 MB) for meanpos
__device__ __nv_bfloat16 g_hi[(size_t)BN * DD];   // bf16 high part (8 MB)
__device__ __nv_bfloat16 g_lo[(size_t)BN * DD];   // bf16 low  part (8 MB)
__device__ float g_sq[BN];
__device__ int   g_lab[BN];
__device__ float g_mean[BN];                      // mean positive distance
__device__ int   g_pcnt[BN];                      // positive count (incl. self)
__device__ int   g_minsh[BN];                     // min semi-hard dist (float bits)

// ---------------- helpers ----------------
__device__ __forceinline__ uint32_t smem_u32(const void* p) {
    uint32_t a;
    asm("{ .reg .u64 t; cvta.to.shared.u64 t, %1; cvt.u32.u64 %0, t; }" : "=r"(a) : "l"(p));
    return a;
}
__device__ __forceinline__ void cp_async16(uint32_t dst, const void* src) {
    asm volatile("cp.async.cg.shared.global [%0], [%1], 16;" :: "r"(dst), "l"(src) : "memory");
}
#define CP_COMMIT() asm volatile("cp.async.commit_group;" ::: "memory")
#define CP_WAIT1()  asm volatile("cp.async.wait_group 1;" ::: "memory")
#define CP_WAIT0()  asm volatile("cp.async.wait_group 0;" ::: "memory")

__device__ __forceinline__ void ldm_x4(uint32_t* r, uint32_t addr) {
    asm volatile("ldmatrix.sync.aligned.m8n8.x4.shared.b16 {%0,%1,%2,%3}, [%4];"
        : "=r"(r[0]), "=r"(r[1]), "=r"(r[2]), "=r"(r[3]) : "r"(addr));
}
__device__ __forceinline__ void mma16816(float* c, const uint32_t* a, const uint32_t* b) {
    asm volatile(
        "mma.sync.aligned.m16n8k16.row.col.f32.bf16.bf16.f32 "
        "{%0,%1,%2,%3}, {%4,%5,%6,%7}, {%8,%9}, {%0,%1,%2,%3};"
        : "+f"(c[0]), "+f"(c[1]), "+f"(c[2]), "+f"(c[3])
        : "r"(a[0]), "r"(a[1]), "r"(a[2]), "r"(a[3]), "r"(b[0]), "r"(b[1]));
}

// ---------------- labels + min init ----------------
__global__ void k_labels(const long long* __restrict__ lab) {
    int i = blockIdx.x * blockDim.x + threadIdx.x;
    if (i < BN) {
        g_lab[i] = (int)lab[i];
        g_minsh[i] = INF_BITS;
    }
}

// ---------------- normalize: fp32 + bf16 hi/lo split ----------------
__global__ void k_norm(const float* __restrict__ X) {
    int row = blockIdx.x;
    int t = threadIdx.x;
    const float4* xr = (const float4*)(X + (size_t)row * DD);
    float4 v = xr[t];
    float ss = v.x * v.x + v.y * v.y + v.z * v.z + v.w * v.w;
    #pragma unroll
    for (int off = 16; off > 0; off >>= 1)
        ss += __shfl_xor_sync(0xffffffffu, ss, off);
    __shared__ float ws[4];
    if ((t & 31) == 0) ws[t >> 5] = ss;
    __syncthreads();
    float tot = ws[0] + ws[1] + ws[2] + ws[3];
    float den = fmaxf(sqrtf(tot), 1e-12f);
    float s = 1.0f / den;
    v.x *= s; v.y *= s; v.z *= s; v.w *= s;
    ((float4*)(g_fn + (size_t)row * DD))[t] = v;

    float f[4] = {v.x, v.y, v.z, v.w};
    __nv_bfloat16 h[4], l[4];
    #pragma unroll
    for (int q = 0; q < 4; q++) {
        h[q] = __float2bfloat16(f[q]);
        l[q] = __float2bfloat16(f[q] - __bfloat162float(h[q]));
    }
    __nv_bfloat162* hp = (__nv_bfloat162*)(g_hi + (size_t)row * DD);
    __nv_bfloat162* lp = (__nv_bfloat162*)(g_lo + (size_t)row * DD);
    hp[2 * t]     = __halves2bfloat162(h[0], h[1]);
    hp[2 * t + 1] = __halves2bfloat162(h[2], h[3]);
    lp[2 * t]     = __halves2bfloat162(l[0], l[1]);
    lp[2 * t + 1] = __halves2bfloat162(l[2], l[3]);
    if (t == 0) g_sq[row] = tot * s * s;
}

// ---------------- mean positive distance per anchor (R2-proven) ----------------
__global__ __launch_bounds__(256) void k_meanpos() {
    int i = blockIdx.x;
    int tid = threadIdx.x;
    int w = tid >> 5;
    int lane = tid & 31;

    __shared__ float fi[DD];
    #pragma unroll
    for (int k = tid; k < DD; k += 256) fi[k] = g_fn[(size_t)i * DD + k];
    __shared__ float wsum[8];
    __shared__ int   wcnt[8];
    int li = g_lab[i];
    float sqi = g_sq[i];
    __syncthreads();

    float psum = 0.0f;
    int   pcnt = 0;
    for (int j = w; j < BN; j += 8) {
        int lj = g_lab[j];                 // warp-uniform
        if (lj == li) {
            const float* fj = g_fn + (size_t)j * DD;
            float dot = 0.0f;
            #pragma unroll
            for (int k = lane; k < DD; k += 32)
                dot = fmaf(fi[k], fj[k], dot);
            #pragma unroll
            for (int off = 16; off > 0; off >>= 1)
                dot += __shfl_xor_sync(0xffffffffu, dot, off);
            float d2 = sqi + g_sq[j] - 2.0f * dot;
            float d = (j == i) ? 0.0f : sqrtf(fmaxf(d2, 0.0f));
            psum += d;
            pcnt += 1;
        }
    }
    if (lane == 0) { wsum[w] = psum; wcnt[w] = pcnt; }
    __syncthreads();
    if (tid == 0) {
        float ts = 0.0f; int tc = 0;
        #pragma unroll
        for (int q = 0; q < 8; q++) { ts += wsum[q]; tc += wcnt[q]; }
        g_pcnt[i] = tc;
        g_mean[i] = ts / (float)tc;        // tc >= 1 (self)
    }
}

// ---------------- fused HMMA distance tiles + semi-hard min ----------------
// Upper-triangle tiles. D = Ahi·Bhi^T + Ahi·Blo^T + Alo·Bhi^T, f32 accum.
// Epilogue: distances into smem Dt, then row-pass + col-pass semi-hard
// reduction -> atomicMin(g_minsh). No g_dist materialization.
extern __shared__ char dsm[];
__global__ __launch_bounds__(256) void k_gemm_fused() {
    int bi = blockIdx.y;
    int bj = blockIdx.x;
    if (bj < bi) return;

    int tid = threadIdx.x;
    int wid = tid >> 5;
    int lid = tid & 31;
    int row0 = bi * 128;
    int col0 = bj * 128;
    int wm = (wid & 3) * 32;      // warp m offset
    int wn = (wid >> 2) * 64;     // warp n offset

    __shared__ float s_sqr[128], s_sqc[128];
    __shared__ float s_rmean[128], s_cmean[128];
    __shared__ int   s_rlab[128], s_clab[128];
    if (tid < 128) {
        s_sqr[tid]   = g_sq[row0 + tid];
        s_sqc[tid]   = g_sq[col0 + tid];
        s_rmean[tid] = g_mean[row0 + tid];
        s_cmean[tid] = g_mean[col0 + tid];
        s_rlab[tid]  = g_lab[row0 + tid];
        s_clab[tid]  = g_lab[col0 + tid];
    }

    uint32_t sb = smem_u32(dsm);

    const __nv_bfloat16* bases[4];
    bases[0] = g_hi + (size_t)row0 * DD;
    bases[1] = g_lo + (size_t)row0 * DD;
    bases[2] = g_hi + (size_t)col0 * DD;
    bases[3] = g_lo + (size_t)col0 * DD;

    auto issue_stage = [&](int kt, int buf) {
        uint32_t dst0 = sb + buf * STAGE_B;
        #pragma unroll
        for (int i = 0; i < 16; i++) {
            int idx = tid + i * 256;
            int mtx = idx >> 10;
            int rem = idx & 1023;
            int r = rem >> 3;
            int e = rem & 7;
            const void* src = bases[mtx] + (size_t)r * DD + kt * 64 + e * 8;
            cp_async16(dst0 + mtx * TILE_B + r * SROW + e * 16, src);
        }
        CP_COMMIT();
    };

    float acc[2][8][4];
    #pragma unroll
    for (int mt = 0; mt < 2; mt++)
        #pragma unroll
        for (int nt = 0; nt < 8; nt++)
            #pragma unroll
            for (int q = 0; q < 4; q++) acc[mt][nt][q] = 0.0f;

    int a_r = lid & 15;
    int a_c = (lid >> 4) * 8;
    int b_r = (lid & 7) + ((lid & 16) >> 1);
    int b_c = (lid & 8);

    issue_stage(0, 0);

    for (int kt = 0; kt < 8; kt++) {
        int cur = kt & 1;
        if (kt + 1 < 8) { issue_stage(kt + 1, cur ^ 1); CP_WAIT1(); }
        else            { CP_WAIT0(); }
        __syncthreads();

        uint32_t base = sb + cur * STAGE_B;
        uint32_t aHi = base + 0 * TILE_B;
        uint32_t aLo = base + 1 * TILE_B;
        uint32_t bHi = base + 2 * TILE_B;
        uint32_t bLo = base + 3 * TILE_B;

        #pragma unroll
        for (int ks = 0; ks < 4; ks++) {
            int kcol = ks * 16;
            uint32_t ahi[2][4], alo[2][4];
            #pragma unroll
            for (int mt = 0; mt < 2; mt++) {
                uint32_t off = (uint32_t)(wm + mt * 16 + a_r) * SROW + (kcol + a_c) * 2;
                ldm_x4(ahi[mt], aHi + off);
                ldm_x4(alo[mt], aLo + off);
            }
            #pragma unroll
            for (int ntp = 0; ntp < 4; ntp++) {
                uint32_t offb = (uint32_t)(wn + ntp * 16 + b_r) * SROW + (kcol + b_c) * 2;
                uint32_t bh[4], bl[4];
                ldm_x4(bh, bHi + offb);
                ldm_x4(bl, bLo + offb);
                #pragma unroll
                for (int mt = 0; mt < 2; mt++) {
                    #pragma unroll
                    for (int s = 0; s < 2; s++) {
                        float* c = acc[mt][2 * ntp + s];
                        mma16816(c, ahi[mt], bh + 2 * s);
                        mma16816(c, ahi[mt], bl + 2 * s);
                        mma16816(c, alo[mt], bh + 2 * s);
                    }
                }
            }
        }
        __syncthreads();
    }

    // ---- distances into smem Dt (reuses stage buffers) ----
    float* Dt = (float*)dsm;   // 128 x 132 floats = 67.6 KB < DYN_SMEM
    int g  = lid >> 2;
    int t4 = lid & 3;
    #pragma unroll
    for (int mt = 0; mt < 2; mt++) {
        #pragma unroll
        for (int nt = 0; nt < 8; nt++) {
            int rr = wm + mt * 16 + g;
            int cc = wn + nt * 8 + t4 * 2;
            float* c = acc[mt][nt];
            float d2;
            d2 = s_sqr[rr]     + s_sqc[cc]     - 2.0f * c[0];
            Dt[rr * 132 + cc]           = sqrtf(fmaxf(d2, 0.0f));
            d2 = s_sqr[rr]     + s_sqc[cc + 1] - 2.0f * c[1];
            Dt[rr * 132 + cc + 1]       = sqrtf(fmaxf(d2, 0.0f));
            d2 = s_sqr[rr + 8] + s_sqc[cc]     - 2.0f * c[2];
            Dt[(rr + 8) * 132 + cc]     = sqrtf(fmaxf(d2, 0.0f));
            d2 = s_sqr[rr + 8] + s_sqc[cc + 1] - 2.0f * c[3];
            Dt[(rr + 8) * 132 + cc + 1] = sqrtf(fmaxf(d2, 0.0f));
        }
    }
    __syncthreads();

    // ---- row pass: anchors row0+row, negatives among this tile's cols ----
    {
        int row = tid >> 1, half = tid & 1;
        int   rl = s_rlab[row];
        float rm = s_rmean[row];
        float v = INF;
        const float* p = Dt + row * 132 + half * 64;
        #pragma unroll 8
        for (int c = 0; c < 64; c++) {
            int cc = half * 64 + c;
            float d = p[c];
            if (s_clab[cc] != rl && d > rm) v = fminf(v, d);
        }
        v = fminf(v, __shfl_xor_sync(0xffffffffu, v, 1));
        if (half == 0 && v < 1e37f)
            atomicMin(&g_minsh[row0 + row], __float_as_int(v));
    }
    // ---- col pass: anchors col0+cc, negatives among this tile's rows ----
    {
        int cc = tid >> 1, half = tid & 1;
        int   cl = s_clab[cc];
        float cm = s_cmean[cc];
        float v = INF;
        #pragma unroll 8
        for (int k = 0; k < 64; k++) {
            int rr = half * 64 + k;
            float d = Dt[rr * 132 + cc];
            if (s_rlab[rr] != cl && d > cm) v = fminf(v, d);
        }
        v = fminf(v, __shfl_xor_sync(0xffffffffu, v, 1));
        if (half == 0 && v < 1e37f)
            atomicMin(&g_minsh[col0 + cc], __float_as_int(v));
    }
}

// ---------------- deterministic final reduction ----------------
__global__ void k_final(float* __restrict__ out) {
    int t = threadIdx.x;
    float s = 0.0f;
    int   c = 0;
    for (int j = t; j < BN; j += 256) {
        int pc = g_pcnt[j];
        int mb = g_minsh[j];
        bool valid  = (pc > 1) && (pc < BN);
        bool has_sh = (mb != INF_BITS);
        if (valid && has_sh) {
            s += fmaxf(g_mean[j] - __int_as_float(mb) + MARGIN, 0.0f);
            c += 1;
        }
    }
    #pragma unroll
    for (int off = 16; off > 0; off >>= 1) {
        s += __shfl_xor_sync(0xffffffffu, s, off);
        c += __shfl_xor_sync(0xffffffffu, c, off);
    }
    __shared__ float ws[8];
    __shared__ int   wc[8];
    int warp = t >> 5;
    if ((t & 31) == 0) { ws[warp] = s; wc[warp] = c; }
    __syncthreads();
    if (t == 0) {
        float ts = 0.0f; int tc = 0;
        #pragma unroll
        for (int w = 0; w < 8; w++) { ts += ws[w]; tc += wc[w]; }
        out[0] = (tc > 0) ? ts / (float)tc : 0.0f;
    }
}

extern "C" void kernel_launch(void* const* d_in, const int* in_sizes, int n_in,
                              void* d_out, int out_size) {
    const float*     X   = (const float*)d_in[0];
    const long long* lab = (const long long*)d_in[1];
    float*           out = (float*)d_out;

    static int s_attr_done = 0;
    if (!s_attr_done) {
        cudaFuncSetAttribute(k_gemm_fused,
                             cudaFuncAttributeMaxDynamicSharedMemorySize, DYN_SMEM);
        s_attr_done = 1;
    }

    k_labels<<<(BN + 255) / 256, 256>>>(lab);
    k_norm<<<BN, 128>>>(X);
    k_meanpos<<<BN, 256>>>();
    dim3 grid(BN / 128, BN / 128);
    k_gemm_fused<<<grid, 256, DYN_SMEM>>>();
    k_final<<<1, 256>>>(out);
}